// round 14
// baseline (speedup 1.0000x reference)
#include <cuda_runtime.h>

#define T_STEPS 1000
#define BATCH   4096
#define IN_SZ   8
#define HID     50
#define OUT_SZ  6
#define NT      32            // ONE warp per block; lane owns rows {lane, lane+32}
#define GB      2             // batch elements per block (share weight regs)
#define VW      64            // v width: [r(50) | x(8) | dead(6)]
#define NPAIR   30            // 60-col weight row = 30 f32x2 pairs
#define DT_F    0.1f

typedef unsigned long long ull;

__device__ __forceinline__ ull pack2(float lo, float hi) {
    ull u; asm("mov.b64 %0, {%1, %2};" : "=l"(u) : "f"(lo), "f"(hi)); return u;
}
__device__ __forceinline__ void unpack2(ull u, float& lo, float& hi) {
    asm("mov.b64 {%0, %1}, %2;" : "=f"(lo), "=f"(hi) : "l"(u));
}
#define FMA2(acc, a, b) asm("fma.rn.f32x2 %0, %1, %2, %0;" : "+l"(acc) : "l"(a), "l"(b))
#define ADD2(d, a, b)   asm("add.rn.f32x2 %0, %1, %2;" : "=l"(d) : "l"(a), "l"(b))

__global__ void __launch_bounds__(NT, 11) biornn_kernel(  // 186-reg cap, est ~166: no spill
    const float* __restrict__ x,      // (T, B, 8)
    const float* __restrict__ Win,    // (50, 8)
    const float* __restrict__ Wrec,   // (50, 50)
    const float* __restrict__ bias,   // (50,)
    const float* __restrict__ Wow,    // (6, 50)
    const float* __restrict__ Wob,    // (6,)
    float* __restrict__ out)          // (T, B, 6)
{
    __shared__ __align__(16) float v_s[2][GB][VW];   // 1 KB

    const int lane = threadIdx.x;     // 0..31
    const int b0   = blockIdx.x * GB;

    // row0 = lane (always hidden); row1 = lane+32:
    //   lane<18  -> row1 32..49 hidden
    //   18..23   -> row1 50..55 output
    //   24..31   -> row1 56..63 dead -> x producer for x[b][lane-24]
    const bool r1_hid  = (lane < 18);
    const bool r1_out  = (lane >= 18) && (lane < 24);
    const bool is_prod = (lane >= 24);

    for (int i = lane; i < 2 * GB * VW; i += NT) ((float*)v_s)[i] = 0.f;

    // ---- two 60-col weight rows packed into 2x30 ull pairs ----
    ull w0[NPAIR], w1[NPAIR];
    ull bj0p, bj1p;
    {
        const float* wr = Wrec + lane * HID;           // row0 always hidden
#pragma unroll
        for (int i = 0; i < 25; i++) w0[i] = pack2(wr[2 * i], wr[2 * i + 1]);
        const float* wi = Win + lane * IN_SZ;
#pragma unroll
        for (int i = 0; i < 4; i++) w0[25 + i] = pack2(wi[2 * i], wi[2 * i + 1]);
        w0[29] = 0ULL;
        bj0p = pack2(bias[lane], 0.f);

        if (r1_hid) {
            const int r1 = lane + 32;
            const float* wr1 = Wrec + r1 * HID;
#pragma unroll
            for (int i = 0; i < 25; i++) w1[i] = pack2(wr1[2 * i], wr1[2 * i + 1]);
            const float* wi1 = Win + r1 * IN_SZ;
#pragma unroll
            for (int i = 0; i < 4; i++) w1[25 + i] = pack2(wi1[2 * i], wi1[2 * i + 1]);
            w1[29] = 0ULL;
            bj1p = pack2(bias[r1], 0.f);
        } else if (r1_out) {
            const float* wo = Wow + (lane - 18) * HID;
#pragma unroll
            for (int i = 0; i < 25; i++) w1[i] = pack2(wo[2 * i], wo[2 * i + 1]);
#pragma unroll
            for (int i = 25; i < NPAIR; i++) w1[i] = 0ULL;
            bj1p = pack2(Wob[lane - 18], 0.f);
        } else {
#pragma unroll
            for (int i = 0; i < NPAIR; i++) w1[i] = 0ULL;
            bj1p = 0ULL;
        }
    }

    // ---- branchless 2-deep x pipeline (producers: lanes 24..31) ----
    const int xi = is_prod ? (lane - 24) : 0;
    const float* xptr = x + (size_t)b0 * IN_SZ + xi;
    const size_t XS = (size_t)BATCH * IN_SZ;
    float xA[GB], xB[GB];
#pragma unroll
    for (int g = 0; g < GB; g++) { xA[g] = xptr[g * IN_SZ]; xB[g] = xptr[XS + g * IN_SZ]; }
    xptr += 2 * XS;

    // STS slots: slot0 = lane (rows 0..31). slot1: hidden -> lane+32;
    // out lanes -> dead 58..63; producers -> 50..57.
    const int slot1 = r1_hid ? (lane + 32) : (is_prod ? (lane + 26) : (lane + 40));

    float* op = out + (r1_out ? ((size_t)b0 * OUT_SZ + (lane - 18)) : 0);

    float*            sbA = &v_s[0][0][0];
    float*            sbB = &v_s[1][0][0];
    const ulonglong2* vpA = reinterpret_cast<const ulonglong2*>(&v_s[0][0][0]);
    const ulonglong2* vpB = reinterpret_cast<const ulonglong2*>(&v_s[1][0][0]);

    float h0[GB], h1[GB];
#pragma unroll
    for (int g = 0; g < GB; g++) { h0[g] = 0.f; h1[g] = 0.f; }

    __syncwarp();

#pragma unroll 1
    for (int t = 0; t < T_STEPS; t++) {
        // publish both v entries per batch (branchless; out lanes write dead slots)
#pragma unroll
        for (int g = 0; g < GB; g++) {
            sbA[g * VW + lane]  = fmaxf(h0[g], 0.f);
            sbA[g * VW + slot1] = is_prod ? xA[g] : fmaxf(h1[g], 0.f);
        }

        __syncwarp();

        // advance x pipeline (pointer clamped near the end)
#pragma unroll
        for (int g = 0; g < GB; g++) { xA[g] = xB[g]; xB[g] = xptr[g * IN_SZ]; }
        if (t < T_STEPS - 3) xptr += XS;

        // GB x 2 dots: 15 broadcast LDS.128 feed 60 FMA2 (4 chains) per batch
        float s0[GB], s1[GB];
#pragma unroll
        for (int g = 0; g < GB; g++) {
            const ulonglong2* vp = vpA + g * (VW / 4);
            ull p0 = bj0p, p1 = 0ULL, q0 = bj1p, q1 = 0ULL;
#pragma unroll
            for (int kk = 0; kk < 15; kk++) {
                const ulonglong2 v2 = vp[kk];
                FMA2(p0, w0[2 * kk],     v2.x);
                FMA2(p1, w0[2 * kk + 1], v2.y);
                FMA2(q0, w1[2 * kk],     v2.x);
                FMA2(q1, w1[2 * kk + 1], v2.y);
            }
            ADD2(p0, p0, p1);
            ADD2(q0, q0, q1);
            float al, ah, bl, bh;
            unpack2(p0, al, ah);  s0[g] = al + ah;
            unpack2(q0, bl, bh);  s1[g] = bl + bh;
        }

        if (r1_out) {
#pragma unroll
            for (int g = 0; g < GB; g++) op[g * OUT_SZ] = s1[g];
        }
        op += (size_t)BATCH * OUT_SZ;

#pragma unroll
        for (int g = 0; g < GB; g++) {
            h0[g] = fmaf(DT_F, s0[g] - h0[g], h0[g]);
            h1[g] = fmaf(DT_F, s1[g] - h1[g], h1[g]);   // garbage-but-finite for out/prod lanes
        }

        // swap double buffers
        float* ts = sbA; sbA = sbB; sbB = ts;
        const ulonglong2* tv = vpA; vpA = vpB; vpB = tv;
    }
}

extern "C" void kernel_launch(void* const* d_in, const int* in_sizes, int n_in,
                              void* d_out, int out_size) {
    const float* x    = (const float*)d_in[0];
    const float* Win  = (const float*)d_in[1];
    const float* Wrec = (const float*)d_in[2];
    const float* bias = (const float*)d_in[3];
    const float* Wow  = (const float*)d_in[4];
    const float* Wob  = (const float*)d_in[5];
    float* out = (float*)d_out;

    biornn_kernel<<<BATCH / GB, NT>>>(x, Win, Wrec, bias, Wow, Wob, out);
}

// round 15
// speedup vs baseline: 1.2697x; 1.2697x over previous
#include <cuda_runtime.h>

#define T_STEPS 1000
#define BATCH   4096
#define IN_SZ   8
#define HID     50
#define OUT_SZ  6
#define NT      32            // ONE warp per block; lane owns rows {lane, lane+32}
#define GB      4             // batch elements per block (share weight regs)
#define VW      64            // v width: [r(50) | x(8) | dead(6)]
#define NPAIR   30            // 60-col weight row = 30 f32x2 pairs
#define DT_F    0.1f

typedef unsigned long long ull;

__device__ __forceinline__ ull pack2(float lo, float hi) {
    ull u; asm("mov.b64 %0, {%1, %2};" : "=l"(u) : "f"(lo), "f"(hi)); return u;
}
__device__ __forceinline__ void unpack2(ull u, float& lo, float& hi) {
    asm("mov.b64 {%0, %1}, %2;" : "=f"(lo), "=f"(hi) : "l"(u));
}
#define FMA2(acc, a, b) asm("fma.rn.f32x2 %0, %1, %2, %0;" : "+l"(acc) : "l"(a), "l"(b))
#define ADD2(d, a, b)   asm("add.rn.f32x2 %0, %1, %2;" : "=l"(d) : "l"(a), "l"(b))

__global__ void __launch_bounds__(NT, 8) biornn_kernel(   // 256-reg cap
    const float* __restrict__ x,      // (T, B, 8)
    const float* __restrict__ Win,    // (50, 8)
    const float* __restrict__ Wrec,   // (50, 50)
    const float* __restrict__ bias,   // (50,)
    const float* __restrict__ Wow,    // (6, 50)
    const float* __restrict__ Wob,    // (6,)
    float* __restrict__ out)          // (T, B, 6)
{
    __shared__ __align__(16) float v_s[2][GB][VW];   // 2 KB

    const int lane = threadIdx.x;     // 0..31
    const int b0   = blockIdx.x * GB;

    // row0 = lane (always hidden); row1 = lane+32:
    //   lane<18 -> hidden 32..49; 18..23 -> out 50..55; 24..31 -> x producer
    const bool r1_hid  = (lane < 18);
    const bool r1_out  = (lane >= 18) && (lane < 24);
    const bool is_prod = (lane >= 24);

    for (int i = lane; i < 2 * GB * VW; i += NT) ((float*)v_s)[i] = 0.f;

    // ---- two 60-col weight rows packed into 2x30 ull pairs ----
    ull w0[NPAIR], w1[NPAIR];
    ull bj0p, bj1p;
    {
        const float* wr = Wrec + lane * HID;           // row0 always hidden
#pragma unroll
        for (int i = 0; i < 25; i++) w0[i] = pack2(wr[2 * i], wr[2 * i + 1]);
        const float* wi = Win + lane * IN_SZ;
#pragma unroll
        for (int i = 0; i < 4; i++) w0[25 + i] = pack2(wi[2 * i], wi[2 * i + 1]);
        w0[29] = 0ULL;
        bj0p = pack2(bias[lane], 0.f);

        if (r1_hid) {
            const int r1 = lane + 32;
            const float* wr1 = Wrec + r1 * HID;
#pragma unroll
            for (int i = 0; i < 25; i++) w1[i] = pack2(wr1[2 * i], wr1[2 * i + 1]);
            const float* wi1 = Win + r1 * IN_SZ;
#pragma unroll
            for (int i = 0; i < 4; i++) w1[25 + i] = pack2(wi1[2 * i], wi1[2 * i + 1]);
            w1[29] = 0ULL;
            bj1p = pack2(bias[r1], 0.f);
        } else if (r1_out) {
            const float* wo = Wow + (lane - 18) * HID;
#pragma unroll
            for (int i = 0; i < 25; i++) w1[i] = pack2(wo[2 * i], wo[2 * i + 1]);
#pragma unroll
            for (int i = 25; i < NPAIR; i++) w1[i] = 0ULL;
            bj1p = pack2(Wob[lane - 18], 0.f);
        } else {
#pragma unroll
            for (int i = 0; i < NPAIR; i++) w1[i] = 0ULL;
            bj1p = 0ULL;
        }
    }

    // ---- branchless 2-deep x pipeline (producers: lanes 24..31) ----
    const int xi = is_prod ? (lane - 24) : 0;
    const float* xptr = x + (size_t)b0 * IN_SZ + xi;
    const size_t XS = (size_t)BATCH * IN_SZ;
    float xA[GB], xB[GB];
#pragma unroll
    for (int g = 0; g < GB; g++) { xA[g] = xptr[g * IN_SZ]; xB[g] = xptr[XS + g * IN_SZ]; }
    xptr += 2 * XS;

    // STS slots: slot0 = lane; slot1: hidden -> lane+32; prod -> 50..57; out -> dead 58..63
    const int slot1 = r1_hid ? (lane + 32) : (is_prod ? (lane + 26) : (lane + 40));

    float* op = out + (r1_out ? ((size_t)b0 * OUT_SZ + (lane - 18)) : 0);

    float*            sbA = &v_s[0][0][0];
    float*            sbB = &v_s[1][0][0];
    const ulonglong2* vpA = reinterpret_cast<const ulonglong2*>(&v_s[0][0][0]);
    const ulonglong2* vpB = reinterpret_cast<const ulonglong2*>(&v_s[1][0][0]);

    float h0[GB], h1[GB];
#pragma unroll
    for (int g = 0; g < GB; g++) { h0[g] = 0.f; h1[g] = 0.f; }

    __syncwarp();

#pragma unroll 1
    for (int t = 0; t < T_STEPS; t++) {
        // publish both v entries per batch (branchless)
#pragma unroll
        for (int g = 0; g < GB; g++) {
            sbA[g * VW + lane]  = fmaxf(h0[g], 0.f);
            sbA[g * VW + slot1] = is_prod ? xA[g] : fmaxf(h1[g], 0.f);
        }

        __syncwarp();

        // advance x pipeline (pointer clamped near the end)
#pragma unroll
        for (int g = 0; g < GB; g++) { xA[g] = xB[g]; xB[g] = xptr[g * IN_SZ]; }
        if (t < T_STEPS - 3) xptr += XS;

        // chunk-major interleave across batches with 1-chunk LDS lookahead.
        // FMA2 order pairs same-v operands (p0,q0 share v.x; p1,q1 share v.y)
        // to maximize operand-reuse-cache hits (RF bank pressure 3 -> ~2).
        ull p0[GB], p1[GB], q0[GB], q1[GB];
        ulonglong2 cur[GB];
#pragma unroll
        for (int g = 0; g < GB; g++) {
            p0[g] = bj0p; p1[g] = 0ULL; q0[g] = bj1p; q1[g] = 0ULL;
            cur[g] = vpA[g * (VW / 4)];            // chunk 0
        }
#pragma unroll
        for (int kk = 0; kk < 15; kk++) {
#pragma unroll
            for (int g = 0; g < GB; g++) {
                const ulonglong2 v2 = cur[g];
                if (kk < 14) cur[g] = vpA[g * (VW / 4) + kk + 1];   // lookahead
                FMA2(p0[g], w0[2 * kk], v2.x);
                FMA2(q0[g], w1[2 * kk], v2.x);     // shares v2.x (reuse)
                if (kk < 14) {                      // chunk 14 pair: cols 58,59 = all-zero
                    FMA2(p1[g], w0[2 * kk + 1], v2.y);
                    FMA2(q1[g], w1[2 * kk + 1], v2.y);
                }
            }
        }

        float s0[GB], s1[GB];
#pragma unroll
        for (int g = 0; g < GB; g++) {
            ADD2(p0[g], p0[g], p1[g]);
            ADD2(q0[g], q0[g], q1[g]);
            float al, ah, bl, bh;
            unpack2(p0[g], al, ah);  s0[g] = al + ah;
            unpack2(q0[g], bl, bh);  s1[g] = bl + bh;
        }

        if (r1_out) {
#pragma unroll
            for (int g = 0; g < GB; g++) op[g * OUT_SZ] = s1[g];
        }
        op += (size_t)BATCH * OUT_SZ;

#pragma unroll
        for (int g = 0; g < GB; g++) {
            h0[g] = fmaf(DT_F, s0[g] - h0[g], h0[g]);
            h1[g] = fmaf(DT_F, s1[g] - h1[g], h1[g]);   // garbage-but-finite for out/prod lanes
        }

        // swap double buffers
        float* ts = sbA; sbA = sbB; sbB = ts;
        const ulonglong2* tv = vpA; vpA = vpB; vpB = tv;
    }
}

extern "C" void kernel_launch(void* const* d_in, const int* in_sizes, int n_in,
                              void* d_out, int out_size) {
    const float* x    = (const float*)d_in[0];
    const float* Win  = (const float*)d_in[1];
    const float* Wrec = (const float*)d_in[2];
    const float* bias = (const float*)d_in[3];
    const float* Wow  = (const float*)d_in[4];
    const float* Wob  = (const float*)d_in[5];
    float* out = (float*)d_out;

    biornn_kernel<<<BATCH / GB, NT>>>(x, Win, Wrec, bias, Wow, Wob, out);
}